// round 9
// baseline (speedup 1.0000x reference)
#include <cuda_runtime.h>
#include <cuda_bf16.h>
#include <cstdint>

#define HC 4
#define CDIM 256
#define KDIM 1024
#define MDIM 24
#define TMAX_IT 20
#define RMS_EPS 1e-6f
#define SINK_EPS 1e-6f
#define POST_MULT 2.0f
#define TOK 64
#define THREADS 256

// ---- smem byte offsets ----
#define OFF_CS 0                       // 64 tok x 20 floats = 5120
#define OFF_AH 5376                    // A hi bf16 [64 rows x 264 bf16] = 33792
#define OFF_AL 39168                   // A lo
#define OFF_D  5376                    // f fp32 [64][264] = 67584 (aliases A, ends 72960)
#define OFF_B  72960                   // B chunk hi(16KB)+lo(16KB); phase-A bufs alias
#define D_STR  264
#define A_STR  528                     // bytes per A row (264 bf16)
#define XSB(b)  (OFF_B + (b)*12992)    // xs[32][68] floats = 8704
#define PHIB(b) (OFF_B + (b)*12992 + 8704)  // phi[32][32] floats = 4096
#define SMEM_TOTAL 105728

typedef unsigned long long u64;

// W pre-packed, B-fragment-major: [kchunk 0..7][hi(16KB)|lo(16KB)]
// within a 16KB half: [ks 0..1][ns 0..31][lane 0..31][b0,b1 (8B)]
__device__ __align__(16) char g_wpk[8 * 32768];

// ---- helpers ----
__device__ __forceinline__ u64 pk2(float lo, float hi) {
    u64 r; asm("mov.b64 %0, {%1, %2};" : "=l"(r) : "f"(lo), "f"(hi)); return r;
}
__device__ __forceinline__ void upk2(u64 v, float& lo, float& hi) {
    asm("mov.b64 {%0, %1}, %2;" : "=f"(lo), "=f"(hi) : "l"(v));
}
__device__ __forceinline__ u64 fma2(u64 a, u64 b, u64 c) {
    u64 d; asm("fma.rn.f32x2 %0, %1, %2, %3;" : "=l"(d) : "l"(a), "l"(b), "l"(c)); return d;
}
__device__ __forceinline__ float sigmoidf_fast(float v) {
    return __fdividef(1.0f, 1.0f + __expf(-v));
}
__device__ __forceinline__ void split4(float4 v, uint2& h, uint2& l) {
    __nv_bfloat16 ax = __float2bfloat16(v.x), ay = __float2bfloat16(v.y),
                  az = __float2bfloat16(v.z), aw = __float2bfloat16(v.w);
    __nv_bfloat16 bx = __float2bfloat16(v.x - __bfloat162float(ax)),
                  by = __float2bfloat16(v.y - __bfloat162float(ay)),
                  bz = __float2bfloat16(v.z - __bfloat162float(az)),
                  bw = __float2bfloat16(v.w - __bfloat162float(aw));
    h.x = ((uint32_t)__bfloat16_as_ushort(ay) << 16) | __bfloat16_as_ushort(ax);
    h.y = ((uint32_t)__bfloat16_as_ushort(aw) << 16) | __bfloat16_as_ushort(az);
    l.x = ((uint32_t)__bfloat16_as_ushort(by) << 16) | __bfloat16_as_ushort(bx);
    l.y = ((uint32_t)__bfloat16_as_ushort(bw) << 16) | __bfloat16_as_ushort(bz);
}
__device__ __forceinline__ void mma_bf16(float4& d, uint4 a, uint2 b) {
    asm volatile("mma.sync.aligned.m16n8k16.row.col.f32.bf16.bf16.f32 "
        "{%0,%1,%2,%3}, {%4,%5,%6,%7}, {%8,%9}, {%0,%1,%2,%3};"
        : "+f"(d.x), "+f"(d.y), "+f"(d.z), "+f"(d.w)
        : "r"(a.x), "r"(a.y), "r"(a.z), "r"(a.w), "r"(b.x), "r"(b.y));
}

// =====================================================================
// W pack: fragment-major hi/lo bf16 (one-time)
__global__ void w_pack(const float* __restrict__ W) {
    int i = blockIdx.x * 256 + threadIdx.x;
    int n = i >> 8, k = i & 255;
    float v = W[n * 256 + k];
    __nv_bfloat16 h = __float2bfloat16(v);
    __nv_bfloat16 l = __float2bfloat16(v - __bfloat162float(h));
    int kc = k >> 5, ks = (k & 31) >> 4, k_in = k & 15, ns = n >> 3;
    int lane = ((n & 7) << 2) | ((k_in >> 1) & 3);
    int off = (((ks * 32 + ns) * 32 + lane) << 3) + ((k_in >> 3) << 2) + ((k_in & 1) << 1);
    *(__nv_bfloat16*)(g_wpk + kc * 32768 + off)         = h;
    *(__nv_bfloat16*)(g_wpk + kc * 32768 + 16384 + off) = l;
}

// =====================================================================
__global__ __launch_bounds__(THREADS, 2)
void mhc_mma(const float* __restrict__ x, const float* __restrict__ phi,
             const float* __restrict__ bvec, const float* __restrict__ apre_p,
             const float* __restrict__ apost_p, const float* __restrict__ ares_p,
             float* __restrict__ out)
{
    extern __shared__ char smem[];
    float* s_cs = (float*)(smem + OFF_CS);
    const int tid = threadIdx.x, lane = tid & 31, wid = tid >> 5;
    const int tok0 = blockIdx.x * TOK;
    const int t0 = wid * 8;

    const float apre = *apre_p, apost = *apost_p, ares = *ares_p;

    // zero phi pads (m 24..31) in both buffers
    for (int l = tid; l < 512; l += THREADS) {
        int b = l >> 8, ll = l & 255;
        ((float*)(smem + PHIB(b)))[(ll >> 3) * 32 + 24 + (ll & 7)] = 0.0f;
    }

    // ---------- Phase A: logits = x . phi (double-buffered, 32-k chunks) ----------
    u64 acc2[4] = {0ull, 0ull, 0ull, 0ull};
    {
        for (int r = 0; r < 2; r++) {
            int slot = r * THREADS + tid, tk = slot >> 3, kq = slot & 7;
            float4 v = *(const float4*)(x + (size_t)(tok0 + tk) * KDIM + kq * 4);
            float* xs = (float*)(smem + XSB(0));
            xs[(kq*4+0)*68 + tk] = v.x; xs[(kq*4+1)*68 + tk] = v.y;
            xs[(kq*4+2)*68 + tk] = v.z; xs[(kq*4+3)*68 + tk] = v.w;
        }
        for (int l = tid; l < 32 * MDIM; l += THREADS)
            ((float*)(smem + PHIB(0)))[(l / MDIM) * 32 + (l % MDIM)] = phi[l];
    }
    __syncthreads();
    for (int kc = 0; kc < 32; kc++) {
        if (kc < 31) {
            int nb = (kc + 1) & 1, kb = (kc + 1) * 32;
            float* xs = (float*)(smem + XSB(nb));
            for (int r = 0; r < 2; r++) {
                int slot = r * THREADS + tid, tk = slot >> 3, kq = slot & 7;
                float4 v = *(const float4*)(x + (size_t)(tok0 + tk) * KDIM + kb + kq * 4);
                xs[(kq*4+0)*68 + tk] = v.x; xs[(kq*4+1)*68 + tk] = v.y;
                xs[(kq*4+2)*68 + tk] = v.z; xs[(kq*4+3)*68 + tk] = v.w;
            }
            float* ph = (float*)(smem + PHIB(nb));
            for (int l = tid; l < 32 * MDIM; l += THREADS)
                ph[(l / MDIM) * 32 + (l % MDIM)] = phi[kb * MDIM + l];
        }
        const float* xs = (const float*)(smem + XSB(kc & 1));
        const float* ph = (const float*)(smem + PHIB(kc & 1));
        #pragma unroll 8
        for (int k = 0; k < 32; k++) {
            float pm = ph[k * 32 + lane];
            u64 pm2 = pk2(pm, pm);
            ulonglong2 xa = *(const ulonglong2*)(&xs[k * 68 + t0]);
            ulonglong2 xb = *(const ulonglong2*)(&xs[k * 68 + t0 + 4]);
            acc2[0] = fma2(xa.x, pm2, acc2[0]);
            acc2[1] = fma2(xa.y, pm2, acc2[1]);
            acc2[2] = fma2(xb.x, pm2, acc2[2]);
            acc2[3] = fma2(xb.y, pm2, acc2[3]);
        }
        __syncthreads();
    }

    float l8[8];
    #pragma unroll
    for (int j = 0; j < 4; j++) upk2(acc2[j], l8[2*j], l8[2*j+1]);
    const float bm = (lane < MDIM) ? bvec[lane] : 0.0f;
    float yv[8];
    #pragma unroll
    for (int t = 0; t < 8; t++) {
        float s = (lane < MDIM) ? l8[t] * l8[t] : 0.0f;
        s += __shfl_xor_sync(~0u, s, 16); s += __shfl_xor_sync(~0u, s, 8);
        s += __shfl_xor_sync(~0u, s, 4);  s += __shfl_xor_sync(~0u, s, 2);
        s += __shfl_xor_sync(~0u, s, 1);
        yv[t] = l8[t] * rsqrtf(s * (1.0f / 24.0f) + RMS_EPS) + bm;
    }

    // ---------- Phase B: Sinkhorn ----------
    float P[4];
    #pragma unroll
    for (int tp = 0; tp < 4; tp++) {
        int src = 8 + (lane & 15);
        float ra = __shfl_sync(~0u, yv[2*tp], src);
        float rb = __shfl_sync(~0u, yv[2*tp+1], src);
        P[tp] = __expf(ares * ((lane < 16) ? ra : rb));
    }
    #pragma unroll
    for (int it = 0; it < TMAX_IT; it++) {
        #pragma unroll
        for (int tp = 0; tp < 4; tp++) {
            float s1 = P[tp] + __shfl_xor_sync(~0u, P[tp], 1);
            s1 += __shfl_xor_sync(~0u, s1, 2);
            P[tp] = __fdividef(P[tp], s1 + SINK_EPS);
        }
        #pragma unroll
        for (int tp = 0; tp < 4; tp++) {
            float s1 = P[tp] + __shfl_xor_sync(~0u, P[tp], 4);
            s1 += __shfl_xor_sync(~0u, s1, 8);
            P[tp] = __fdividef(P[tp], s1 + SINK_EPS);
        }
    }
    #pragma unroll
    for (int tp = 0; tp < 4; tp++) {
        int tl = t0 + 2*tp;
        if (lane < 16) s_cs[tl * 20 + lane] = P[tp];
        else           s_cs[(tl + 1) * 20 + (lane - 16)] = P[tp];
    }

    // ---------- Phase C: h_post + xin -> A tiles (bf16 hi/lo, row-major pad 264) ----------
    #pragma unroll
    for (int t = 0; t < 8; t++) {
        int tl = t0 + t, tok = tok0 + tl;
        float yp = __shfl_sync(~0u, yv[t], 4 + (lane & 3));
        if (lane < 4) s_cs[tl * 20 + 16 + lane] = POST_MULT * sigmoidf_fast(apost * yp);
        float hp0 = sigmoidf_fast(apre * __shfl_sync(~0u, yv[t], 0));
        float hp1 = sigmoidf_fast(apre * __shfl_sync(~0u, yv[t], 1));
        float hp2 = sigmoidf_fast(apre * __shfl_sync(~0u, yv[t], 2));
        float hp3 = sigmoidf_fast(apre * __shfl_sync(~0u, yv[t], 3));
        const float4* xt = (const float4*)(x + (size_t)tok * KDIM);
        float4 sA = make_float4(0,0,0,0), sB = make_float4(0,0,0,0);
        #pragma unroll
        for (int i = 0; i < HC; i++) {
            float hp = (i==0)?hp0:(i==1)?hp1:(i==2)?hp2:hp3;
            float4 a = xt[i * 64 + lane], b = xt[i * 64 + 32 + lane];
            sA.x = fmaf(hp,a.x,sA.x); sA.y = fmaf(hp,a.y,sA.y);
            sA.z = fmaf(hp,a.z,sA.z); sA.w = fmaf(hp,a.w,sA.w);
            sB.x = fmaf(hp,b.x,sB.x); sB.y = fmaf(hp,b.y,sB.y);
            sB.z = fmaf(hp,b.z,sB.z); sB.w = fmaf(hp,b.w,sB.w);
        }
        uint2 hA, lA, hB, lB;
        split4(sA, hA, lA); split4(sB, hB, lB);
        *(uint2*)(smem + OFF_AH + tl*A_STR + lane*8)       = hA;
        *(uint2*)(smem + OFF_AL + tl*A_STR + lane*8)       = lA;
        *(uint2*)(smem + OFF_AH + tl*A_STR + 256 + lane*8) = hB;
        *(uint2*)(smem + OFF_AL + tl*A_STR + 256 + lane*8) = lB;
    }
    __syncthreads();

    // ---------- Phase D: F = xin @ W^T via mma.sync bf16 (3-product split) ----------
    const int mt = wid & 3;        // m-tile (16 rows), 4 tiles = 64 tokens
    const int nh = wid >> 2;       // n half
    float4 D[16];
    #pragma unroll
    for (int j = 0; j < 16; j++) D[j] = make_float4(0,0,0,0);

    const char* pah = smem + OFF_AH + (mt*16 + (lane>>2))*A_STR + (lane&3)*4;
    const char* pal = smem + OFF_AL + (mt*16 + (lane>>2))*A_STR + (lane&3)*4;

    for (int kc = 0; kc < 8; kc++) {
        // copy 32 KB packed W chunk into smem
        {
            const uint4* src = (const uint4*)(g_wpk + kc * 32768);
            uint4* dst = (uint4*)(smem + OFF_B);
            #pragma unroll
            for (int j = 0; j < 8; j++) dst[j * THREADS + tid] = src[j * THREADS + tid];
        }
        __syncthreads();
        #pragma unroll
        for (int ks = 0; ks < 2; ks++) {
            int gko = (kc * 2 + ks) * 32;   // byte offset of kstep in A row
            uint4 Ah, Al;
            Ah.x = *(const uint32_t*)(pah + gko);
            Ah.y = *(const uint32_t*)(pah + 8*A_STR + gko);
            Ah.z = *(const uint32_t*)(pah + gko + 16);
            Ah.w = *(const uint32_t*)(pah + 8*A_STR + gko + 16);
            Al.x = *(const uint32_t*)(pal + gko);
            Al.y = *(const uint32_t*)(pal + 8*A_STR + gko);
            Al.z = *(const uint32_t*)(pal + gko + 16);
            Al.w = *(const uint32_t*)(pal + 8*A_STR + gko + 16);
            const char* pb = smem + OFF_B + ((ks*32 + nh*16)*32 + lane)*8;
            #pragma unroll
            for (int j = 0; j < 16; j++) {
                uint2 bh = *(const uint2*)(pb + j*256);
                uint2 bl = *(const uint2*)(pb + 16384 + j*256);
                mma_bf16(D[j], Ah, bh);
                mma_bf16(D[j], Al, bh);
                mma_bf16(D[j], Ah, bl);
            }
        }
        __syncthreads();
    }

    // ---------- stage F into s_D fp32 [64][264] (aliases A region) ----------
    float* sD = (float*)(smem + OFF_D);
    {
        int r0 = mt*16 + (lane>>2);
        int cb = nh*128 + (lane&3)*2;
        #pragma unroll
        for (int j = 0; j < 16; j++) {
            int col = cb + j*8;
            *(float2*)&sD[r0*D_STR + col]     = make_float2(D[j].x, D[j].y);
            *(float2*)&sD[(r0+8)*D_STR + col] = make_float2(D[j].z, D[j].w);
        }
    }
    __syncthreads();

    // ---------- epilogue: out = P@x + hpost * f ----------
    const int cx = lane;
    #pragma unroll
    for (int i = 0; i < 8; i++) {
        int tl = t0 + i, tok = tok0 + tl;
        const u64* xb = (const u64*)(x + (size_t)tok * KDIM);
        ulonglong2 xpA[HC], xpB[HC];
        #pragma unroll
        for (int ii = 0; ii < HC; ii++) {
            xpA[ii] = *(const ulonglong2*)(xb + ii * 128 + cx * 2);
            xpB[ii] = *(const ulonglong2*)(xb + ii * 128 + 64 + cx * 2);
        }
        float4 fA = *(const float4*)(sD + tl * D_STR + 4 * cx);
        float4 fB = *(const float4*)(sD + tl * D_STR + 128 + 4 * cx);
        u64* ob = (u64*)(out + (size_t)tok * KDIM);
        #pragma unroll
        for (int o = 0; o < HC; o++) {
            float hp = s_cs[tl * 20 + 16 + o];
            u64 hp2 = pk2(hp, hp);
            u64 r0 = fma2(hp2, pk2(fA.x, fA.y), 0ull);
            u64 r1 = fma2(hp2, pk2(fA.z, fA.w), 0ull);
            u64 r2 = fma2(hp2, pk2(fB.x, fB.y), 0ull);
            u64 r3 = fma2(hp2, pk2(fB.z, fB.w), 0ull);
            #pragma unroll
            for (int ii = 0; ii < HC; ii++) {
                float p = s_cs[tl * 20 + o * 4 + ii];
                u64 p2 = pk2(p, p);
                r0 = fma2(p2, xpA[ii].x, r0); r1 = fma2(p2, xpA[ii].y, r1);
                r2 = fma2(p2, xpB[ii].x, r2); r3 = fma2(p2, xpB[ii].y, r3);
            }
            *(ulonglong2*)(ob + o * 128 + cx * 2)      = make_ulonglong2(r0, r1);
            *(ulonglong2*)(ob + o * 128 + 64 + cx * 2) = make_ulonglong2(r2, r3);
        }
    }
}

// =====================================================================
extern "C" void kernel_launch(void* const* d_in, const int* in_sizes, int n_in,
                              void* d_out, int out_size)
{
    const float* x     = (const float*)d_in[0];
    const float* phi   = (const float*)d_in[1];
    const float* bvec  = (const float*)d_in[2];
    const float* apre  = (const float*)d_in[3];
    const float* apost = (const float*)d_in[4];
    const float* ares  = (const float*)d_in[5];
    const float* W     = (const float*)d_in[6];
    float* out = (float*)d_out;

    int tokens = in_sizes[0] / KDIM;

    static bool attr_set = false;
    if (!attr_set) {
        cudaFuncSetAttribute(mhc_mma, cudaFuncAttributeMaxDynamicSharedMemorySize, SMEM_TOTAL);
        attr_set = true;
    }
    w_pack<<<256, 256>>>(W);
    mhc_mma<<<tokens / TOK, THREADS, SMEM_TOTAL>>>(x, phi, bvec, apre, apost, ares, out);
}